// round 6
// baseline (speedup 1.0000x reference)
#include <cuda_runtime.h>
#include <cuda_fp16.h>
#include <cstdint>
#include <math.h>

// Problem constants
#define NT 8192          // tokens = 4*2048
#define NH 1024          // hidden
#define NE 8             // experts
#define NI 4096          // intermediate
#define NPAIRS (2*NT)    // top-2 pairs

// ==================== PTX helpers ====================
__device__ __forceinline__ void mma16816(float* d, const uint32_t* a, const uint32_t* b) {
    asm volatile("mma.sync.aligned.m16n8k16.row.col.f32.f16.f16.f32 "
        "{%0,%1,%2,%3}, {%4,%5,%6,%7}, {%8,%9}, {%0,%1,%2,%3};"
        : "+f"(d[0]), "+f"(d[1]), "+f"(d[2]), "+f"(d[3])
        : "r"(a[0]), "r"(a[1]), "r"(a[2]), "r"(a[3]), "r"(b[0]), "r"(b[1]));
}
__device__ __forceinline__ void ldsm4(uint32_t* r, uint32_t addr) {
    asm volatile("ldmatrix.sync.aligned.m8n8.x4.shared.b16 {%0,%1,%2,%3}, [%4];"
        : "=r"(r[0]), "=r"(r[1]), "=r"(r[2]), "=r"(r[3]) : "r"(addr));
}
__device__ __forceinline__ uint32_t smem_u32(const void* p) {
    uint32_t a;
    asm("{ .reg .u64 t; cvta.to.shared.u64 t, %1; cvt.u32.u64 %0, t; }" : "=r"(a) : "l"(p));
    return a;
}
#define CP16(sm_addr, gptr) \
    asm volatile("cp.async.ca.shared.global [%0], [%1], 16;" \
                 :: "r"(sm_addr), "l"(gptr) : "memory")
#define CP_COMMIT() asm volatile("cp.async.commit_group;" ::: "memory")
#define CP_WAIT0()  asm volatile("cp.async.wait_group 0;" ::: "memory")

// ==================== device scratch (all 16B-aligned) ====================
__device__ __align__(16) int   g_sel[NT * 2];
__device__ __align__(16) float g_wt[NT * 2];
__device__ __align__(16) int   g_counts[NE];
__device__ __align__(16) int   g_offsets[NE];
__device__ __align__(16) int   g_cursor[NE];
__device__ __align__(16) float g_probsum[NE];
__device__ float g_zsum;
__device__ __align__(16) int   g_pair_tok[NPAIRS];
__device__ __align__(16) float g_pair_w[NPAIRS];

__device__ __align__(16) __half g_x_h[NT * NH];
__device__ __align__(16) __half g_wg_h[NE * NI * NH];
__device__ __align__(16) __half g_wu_h[NE * NI * NH];
__device__ __align__(16) __half g_wd_h[NE * NH * NI];
__device__ __align__(16) __half g_h[(size_t)NPAIRS * NI];

// ==================== init ====================
__global__ void k_init(float* __restrict__ out) {
    int idx = blockIdx.x * blockDim.x + threadIdx.x;
    if (idx < NE) { g_counts[idx] = 0; g_cursor[idx] = 0; g_probsum[idx] = 0.f; }
    if (idx == 0) g_zsum = 0.f;
    const int n = NT * NH;
    for (int i = idx; i < n; i += gridDim.x * blockDim.x) out[i] = 0.f;
}

// ==================== fp32 -> fp16 (device-resolved dst: GB300 ATS trap) ====
__global__ void k_half(const float* __restrict__ src, int which, int n4) {
    __half* dst;
    switch (which) {
        case 0:  dst = g_wg_h; break;
        case 1:  dst = g_wu_h; break;
        case 2:  dst = g_wd_h; break;
        default: dst = g_x_h;  break;
    }
    int i = blockIdx.x * blockDim.x + threadIdx.x;
    if (i >= n4) return;
    float4 v = ((const float4*)src)[i];
    union { __half h[4]; uint2 u; } r;
    r.h[0] = __float2half_rn(v.x);
    r.h[1] = __float2half_rn(v.y);
    r.h[2] = __float2half_rn(v.z);
    r.h[3] = __float2half_rn(v.w);
    ((uint2*)dst)[i] = r.u;
}

// ==================== router (one warp per token) ====================
__global__ void k_router(const float* __restrict__ x, const float* __restrict__ gw) {
    __shared__ float sgw[NE * NH];
    __shared__ float sprob[NE];
    __shared__ float sz;
    int tid = threadIdx.x;
    for (int i = tid; i < NE * NH; i += 256) sgw[i] = gw[i];
    if (tid < NE) sprob[tid] = 0.f;
    if (tid == 0) sz = 0.f;
    __syncthreads();

    int warp = tid >> 5, lane = tid & 31;
    int t = blockIdx.x * 8 + warp;

    float acc[NE];
#pragma unroll
    for (int e = 0; e < NE; e++) acc[e] = 0.f;
    const float* xr = x + (size_t)t * NH;
    for (int j = lane; j < NH; j += 32) {
        float xv = xr[j];
#pragma unroll
        for (int e = 0; e < NE; e++) acc[e] += xv * sgw[e * NH + j];
    }
#pragma unroll
    for (int e = 0; e < NE; e++)
#pragma unroll
        for (int off = 16; off > 0; off >>= 1)
            acc[e] += __shfl_xor_sync(0xffffffffu, acc[e], off);

    if (lane == 0) {
        float m = acc[0];
#pragma unroll
        for (int e = 1; e < NE; e++) m = fmaxf(m, acc[e]);
        float p[NE]; float s = 0.f;
#pragma unroll
        for (int e = 0; e < NE; e++) { p[e] = expf(acc[e] - m); s += p[e]; }
        float inv = 1.f / s;
#pragma unroll
        for (int e = 0; e < NE; e++) p[e] *= inv;

        int i0 = 0; float m0 = p[0];
#pragma unroll
        for (int e = 1; e < NE; e++) if (p[e] > m0) { m0 = p[e]; i0 = e; }
        int i1 = -1; float m1 = -1.f;
#pragma unroll
        for (int e = 0; e < NE; e++) if (e != i0 && p[e] > m1) { m1 = p[e]; i1 = e; }

        float wsum = m0 + m1;
        g_sel[2*t] = i0; g_sel[2*t+1] = i1;
        g_wt[2*t] = m0 / wsum; g_wt[2*t+1] = m1 / wsum;
        atomicAdd(&g_counts[i0], 1);
        atomicAdd(&g_counts[i1], 1);
#pragma unroll
        for (int e = 0; e < NE; e++) atomicAdd(&sprob[e], p[e]);
        float lse = m + logf(s);
        atomicAdd(&sz, lse * lse);
    }
    __syncthreads();
    if (tid < NE) atomicAdd(&g_probsum[tid], sprob[tid]);
    if (tid == 0) atomicAdd(&g_zsum, sz);
}

__global__ void k_offsets() {
    if (threadIdx.x == 0 && blockIdx.x == 0) {
        int s = 0;
        for (int e = 0; e < NE; e++) { g_offsets[e] = s; s += g_counts[e]; }
    }
}

__global__ void k_scatter() {
    int t = blockIdx.x * blockDim.x + threadIdx.x;
    if (t >= NT) return;
#pragma unroll
    for (int k = 0; k < 2; k++) {
        int e = g_sel[2*t + k];
        int pos = atomicAdd(&g_cursor[e], 1);
        int p = g_offsets[e] + pos;
        g_pair_tok[p] = t;
        g_pair_w[p]   = g_wt[2*t + k];
    }
}

// ==================== HMMA GEMM kernels (cp.async + ldmatrix) ====================
#define KB 32                 // K elements per stage
#define PITCH 80              // bytes per smem row: 64 data + 16 pad
#define STAGE 20480
#define TILES_M 64

// ---- pass 1: gate/up GEMM + SwiGLU -> g_h (fp16) ----
// CTA tile M=128 x N=64 (two outputs); 256 threads; grid (TILES_M, NE*64)
__global__ void __launch_bounds__(256) k_ffn1() {
    __shared__ __align__(16) char smc[2 * STAGE];   // A 10240 | Bg 5120 | Bu 5120
    __shared__ int s_tok[128];

    int e  = blockIdx.y >> 6;
    int n0 = (blockIdx.y & 63) * 64;
    int row0 = blockIdx.x * 128;
    int cnt = g_counts[e];
    if (row0 >= cnt) return;
    int base = g_offsets[e];
    int tid = threadIdx.x;

    if (tid < 128) {
        int r = row0 + tid;
        s_tok[tid] = g_pair_tok[base + (r < cnt ? r : cnt - 1)];
    }
    __syncthreads();

    uint32_t sb = smem_u32(smc);

    // cp.async loaders: A rows 2/thread, Bg 1, Bu 1 (16B chunks)
    int a_r0 = tid >> 2;            // 0..63
    int a_r1 = a_r0 + 64;           // 64..127
    int a_c  = tid & 3;
    const __half* pA0 = g_x_h + (size_t)s_tok[a_r0] * NH + a_c * 8;
    const __half* pA1 = g_x_h + (size_t)s_tok[a_r1] * NH + a_c * 8;
    const __half* pBg = g_wg_h + ((size_t)e * NI + n0 + a_r0) * NH + a_c * 8;
    const __half* pBu = g_wu_h + ((size_t)e * NI + n0 + a_r0) * NH + a_c * 8;
    uint32_t sA0 = sb + a_r0 * PITCH + a_c * 16;
    uint32_t sA1 = sb + a_r1 * PITCH + a_c * 16;
    uint32_t sBg = sb + 10240 + a_r0 * PITCH + a_c * 16;
    uint32_t sBu = sb + 15360 + a_r0 * PITCH + a_c * 16;

    int lane = tid & 31, w = tid >> 5;
    int wm = w >> 1, wn = w & 1;
    int r4 = lane >> 2, c2 = lane & 3;

    // ldmatrix lane-base addresses
    uint32_t aA[2], aBgf[2], aBuf[2];
#pragma unroll
    for (int i = 0; i < 2; i++) {
        int row = wm * 32 + i * 16 + (lane & 7) + ((lane >> 3) & 1) * 8;
        aA[i] = sb + row * PITCH + (lane >> 4) * 16;
    }
#pragma unroll
    for (int jj = 0; jj < 2; jj++) {
        int row = wn * 32 + jj * 16 + (lane & 7) + (lane >> 4) * 8;
        uint32_t co = ((lane >> 3) & 1) * 16;
        aBgf[jj] = sb + 10240 + row * PITCH + co;
        aBuf[jj] = sb + 15360 + row * PITCH + co;
    }

    float ag[2][4][4], au[2][4][4];
#pragma unroll
    for (int i = 0; i < 2; i++)
#pragma unroll
        for (int j = 0; j < 4; j++)
#pragma unroll
            for (int q = 0; q < 4; q++) { ag[i][j][q] = 0.f; au[i][j][q] = 0.f; }

    // prologue: stage 0
    CP16(sA0, pA0); CP16(sA1, pA1); CP16(sBg, pBg); CP16(sBu, pBu);
    CP_COMMIT();

    const int KT = NH / KB;   // 32
    for (int kt = 0; kt < KT; kt++) {
        CP_WAIT0();
        __syncthreads();
        if (kt + 1 < KT) {
            int ko = (kt + 1) * KB;
            uint32_t off = ((kt + 1) & 1) * STAGE;
            CP16(sA0 + off, pA0 + ko); CP16(sA1 + off, pA1 + ko);
            CP16(sBg + off, pBg + ko); CP16(sBu + off, pBu + ko);
            CP_COMMIT();
        }
        uint32_t soff = (kt & 1) * STAGE;
#pragma unroll
        for (int kk = 0; kk < 2; kk++) {
            uint32_t koff = soff + kk * 32;
            uint32_t af[2][4];
            ldsm4(af[0], aA[0] + koff);
            ldsm4(af[1], aA[1] + koff);
#pragma unroll
            for (int jj = 0; jj < 2; jj++) {
                uint32_t bg[4], bu[4];
                ldsm4(bg, aBgf[jj] + koff);
                ldsm4(bu, aBuf[jj] + koff);
                int j0 = 2 * jj, j1 = 2 * jj + 1;
                mma16816(ag[0][j0], af[0], bg);     mma16816(ag[0][j1], af[0], bg + 2);
                mma16816(ag[1][j0], af[1], bg);     mma16816(ag[1][j1], af[1], bg + 2);
                mma16816(au[0][j0], af[0], bu);     mma16816(au[0][j1], af[0], bu + 2);
                mma16816(au[1][j0], af[1], bu);     mma16816(au[1][j1], af[1], bu + 2);
            }
        }
        // no trailing sync: next iteration's barrier protects buffer reuse
    }

    // epilogue: h = silu(g)*u -> fp16
#pragma unroll
    for (int i = 0; i < 2; i++)
#pragma unroll
        for (int rr = 0; rr < 2; rr++) {
            int rl = wm * 32 + i * 16 + r4 + rr * 8;
            int r = row0 + rl;
            if (r < cnt) {
                __half* hrow = g_h + (size_t)(base + r) * NI;
#pragma unroll
                for (int j = 0; j < 4; j++) {
                    int col = n0 + wn * 32 + j * 8 + c2 * 2;
                    float g0 = ag[i][j][rr * 2], g1 = ag[i][j][rr * 2 + 1];
                    float u0 = au[i][j][rr * 2], u1 = au[i][j][rr * 2 + 1];
                    float h0 = g0 / (1.f + expf(-g0)) * u0;
                    float h1 = g1 / (1.f + expf(-g1)) * u1;
                    *(__half2*)(hrow + col) = __floats2half2_rn(h0, h1);
                }
            }
        }
}

// ---- pass 2: out[tok] += w * (h @ Wd^T) ----
// CTA tile M=128 x N=128; 256 threads; grid (TILES_M, NE*8)
__global__ void __launch_bounds__(256) k_ffn2(float* __restrict__ out) {
    __shared__ __align__(16) char smc[2 * STAGE];   // A 10240 | B 10240
    __shared__ int   s_tok[128];
    __shared__ float s_w[128];

    int e  = blockIdx.y >> 3;
    int n0 = (blockIdx.y & 7) * 128;
    int row0 = blockIdx.x * 128;
    int cnt = g_counts[e];
    if (row0 >= cnt) return;
    int base = g_offsets[e];
    int tid = threadIdx.x;

    if (tid < 128) {
        int r = row0 + tid;
        s_tok[tid] = (r < cnt) ? g_pair_tok[base + r] : 0;
        s_w[tid]   = (r < cnt) ? g_pair_w[base + r] : 0.f;
    }
    __syncthreads();

    uint32_t sb = smem_u32(smc);

    int a_r0 = tid >> 2;
    int a_r1 = a_r0 + 64;
    int a_c  = tid & 3;
    int rc0 = row0 + a_r0; if (rc0 >= cnt) rc0 = cnt - 1;
    int rc1 = row0 + a_r1; if (rc1 >= cnt) rc1 = cnt - 1;
    const __half* pA0 = g_h + (size_t)(base + rc0) * NI + a_c * 8;
    const __half* pA1 = g_h + (size_t)(base + rc1) * NI + a_c * 8;
    const __half* pB0 = g_wd_h + ((size_t)e * NH + n0 + a_r0) * NI + a_c * 8;
    const __half* pB1 = g_wd_h + ((size_t)e * NH + n0 + a_r1) * NI + a_c * 8;
    uint32_t sA0 = sb + a_r0 * PITCH + a_c * 16;
    uint32_t sA1 = sb + a_r1 * PITCH + a_c * 16;
    uint32_t sB0 = sA0 + 10240;
    uint32_t sB1 = sA1 + 10240;

    int lane = tid & 31, w = tid >> 5;
    int wm = w >> 1, wn = w & 1;
    int r4 = lane >> 2, c2 = lane & 3;

    uint32_t aA[2], aB[4];
#pragma unroll
    for (int i = 0; i < 2; i++) {
        int row = wm * 32 + i * 16 + (lane & 7) + ((lane >> 3) & 1) * 8;
        aA[i] = sb + row * PITCH + (lane >> 4) * 16;
    }
#pragma unroll
    for (int jj = 0; jj < 4; jj++) {
        int row = wn * 64 + jj * 16 + (lane & 7) + (lane >> 4) * 8;
        aB[jj] = sb + 10240 + row * PITCH + ((lane >> 3) & 1) * 16;
    }

    float acc[2][8][4];
#pragma unroll
    for (int i = 0; i < 2; i++)
#pragma unroll
        for (int j = 0; j < 8; j++)
#pragma unroll
            for (int q = 0; q < 4; q++) acc[i][j][q] = 0.f;

    CP16(sA0, pA0); CP16(sA1, pA1); CP16(sB0, pB0); CP16(sB1, pB1);
    CP_COMMIT();

    const int KT = NI / KB;   // 128
    for (int kt = 0; kt < KT; kt++) {
        CP_WAIT0();
        __syncthreads();
        if (kt + 1 < KT) {
            int ko = (kt + 1) * KB;
            uint32_t off = ((kt + 1) & 1) * STAGE;
            CP16(sA0 + off, pA0 + ko); CP16(sA1 + off, pA1 + ko);
            CP16(sB0 + off, pB0 + ko); CP16(sB1 + off, pB1 + ko);
            CP_COMMIT();
        }
        uint32_t soff = (kt & 1) * STAGE;
#pragma unroll
        for (int kk = 0; kk < 2; kk++) {
            uint32_t koff = soff + kk * 32;
            uint32_t af[2][4];
            ldsm4(af[0], aA[0] + koff);
            ldsm4(af[1], aA[1] + koff);
#pragma unroll
            for (int jj = 0; jj < 4; jj++) {
                uint32_t bf[4];
                ldsm4(bf, aB[jj] + koff);
                int j0 = 2 * jj, j1 = 2 * jj + 1;
                mma16816(acc[0][j0], af[0], bf);     mma16816(acc[0][j1], af[0], bf + 2);
                mma16816(acc[1][j0], af[1], bf);     mma16816(acc[1][j1], af[1], bf + 2);
            }
        }
    }

    // epilogue: weighted atomic accumulate into out
#pragma unroll
    for (int i = 0; i < 2; i++)
#pragma unroll
        for (int rr = 0; rr < 2; rr++) {
            int rl = wm * 32 + i * 16 + r4 + rr * 8;
            if (row0 + rl < cnt) {
                int tok = s_tok[rl];
                float wt = s_w[rl];
                float* orow = out + (size_t)tok * NH + n0;
#pragma unroll
                for (int j = 0; j < 8; j++) {
                    int col = wn * 64 + j * 8 + c2 * 2;
                    atomicAdd(&orow[col],     wt * acc[i][j][rr * 2]);
                    atomicAdd(&orow[col + 1], wt * acc[i][j][rr * 2 + 1]);
                }
            }
        }
}

// ==================== losses ====================
__global__ void k_losses(float* __restrict__ out, int out_size) {
    if (threadIdx.x == 0 && blockIdx.x == 0) {
        float lb = 0.f;
        for (int e = 0; e < NE; e++)
            lb += ((float)g_counts[e] / (float)NT) * (g_probsum[e] / (float)NT);
        lb *= (float)NE * 0.01f;
        float z = g_zsum / (float)NT * 0.001f;
        if (out_size > NT * NH)     out[NT * NH]     = lb;
        if (out_size > NT * NH + 1) out[NT * NH + 1] = z;
    }
}

// ==================== launch ====================
extern "C" void kernel_launch(void* const* d_in, const int* in_sizes, int n_in,
                              void* d_out, int out_size) {
    const float* x  = (const float*)d_in[0];
    const float* gw = (const float*)d_in[1];
    const float* wg = (const float*)d_in[2];
    const float* wu = (const float*)d_in[3];
    const float* wd = (const float*)d_in[4];
    float* out = (float*)d_out;

    k_init<<<2048, 256>>>(out);

    const int WN4 = NE * NI * NH / 4;
    k_half<<<(WN4 + 255) / 256, 256>>>(wg, 0, WN4);
    k_half<<<(WN4 + 255) / 256, 256>>>(wu, 1, WN4);
    k_half<<<(WN4 + 255) / 256, 256>>>(wd, 2, WN4);
    const int XN4 = NT * NH / 4;
    k_half<<<(XN4 + 255) / 256, 256>>>(x, 3, XN4);

    k_router<<<NT / 8, 256>>>(x, gw);
    k_offsets<<<1, 32>>>();
    k_scatter<<<(NT + 255) / 256, 256>>>();

    dim3 g1(TILES_M, NE * 64);
    k_ffn1<<<g1, 256>>>();

    dim3 g2(TILES_M, NE * 8);
    k_ffn2<<<g2, 256>>>(out);

    k_losses<<<1, 32>>>(out, out_size);
}

// round 7
// speedup vs baseline: 1.0122x; 1.0122x over previous
#include <cuda_runtime.h>
#include <cuda_fp16.h>
#include <cstdint>
#include <math.h>

// Problem constants
#define NT 8192          // tokens = 4*2048
#define NH 1024          // hidden
#define NE 8             // experts
#define NI 4096          // intermediate
#define NPAIRS (2*NT)    // top-2 pairs

// mma.sync m16n8k16 row.col f32.f16.f16.f32
__device__ __forceinline__ void mma16816(float* d, const uint32_t* a, const uint32_t* b) {
    asm volatile("mma.sync.aligned.m16n8k16.row.col.f32.f16.f16.f32 "
        "{%0,%1,%2,%3}, {%4,%5,%6,%7}, {%8,%9}, {%0,%1,%2,%3};"
        : "+f"(d[0]), "+f"(d[1]), "+f"(d[2]), "+f"(d[3])
        : "r"(a[0]), "r"(a[1]), "r"(a[2]), "r"(a[3]), "r"(b[0]), "r"(b[1]));
}

// ==================== device scratch (all 16B-aligned) ====================
__device__ __align__(16) int   g_sel[NT * 2];
__device__ __align__(16) float g_wt[NT * 2];
__device__ __align__(16) int   g_counts[NE];
__device__ __align__(16) int   g_offsets[NE];
__device__ __align__(16) float g_probsum[NE];
__device__ float g_zsum;
__device__ __align__(16) int   g_pair_tok[NPAIRS];
__device__ __align__(16) float g_pair_w[NPAIRS];

__device__ __align__(16) __half g_x_h[NT * NH];
__device__ __align__(16) __half g_wg_h[NE * NI * NH];
__device__ __align__(16) __half g_wu_h[NE * NI * NH];
__device__ __align__(16) __half g_wd_h[NE * NH * NI];
__device__ __align__(16) __half g_h[(size_t)NPAIRS * NI];

// ==================== fused fp32->fp16 conversion (single launch) ==========
// Device-resolved destinations (GB300 ATS trap: never pass __device__ symbol
// addresses from host). Also zeroes the router accumulators.
#define W4 (NE * NI * NH / 4)    // 8388608 float4-chunks per weight tensor
#define X4 (NT * NH / 4)         // 2097152
__global__ void k_conv(const float* __restrict__ wg, const float* __restrict__ wu,
                       const float* __restrict__ wd, const float* __restrict__ x) {
    long i = (long)blockIdx.x * blockDim.x + threadIdx.x;
    if (blockIdx.x == 0 && threadIdx.x < NE) {
        g_counts[threadIdx.x] = 0;
        g_probsum[threadIdx.x] = 0.f;
        if (threadIdx.x == 0) g_zsum = 0.f;
    }
    const float* src;
    __half* dst;
    long j;
    if (i < W4)            { src = wg; dst = g_wg_h; j = i; }
    else if (i < 2L * W4)  { src = wu; dst = g_wu_h; j = i - W4; }
    else if (i < 3L * W4)  { src = wd; dst = g_wd_h; j = i - 2L * W4; }
    else if (i < 3L * W4 + X4) { src = x; dst = g_x_h; j = i - 3L * W4; }
    else return;
    float4 v = ((const float4*)src)[j];
    union { __half h[4]; uint2 u; } r;
    r.h[0] = __float2half_rn(v.x);
    r.h[1] = __float2half_rn(v.y);
    r.h[2] = __float2half_rn(v.z);
    r.h[3] = __float2half_rn(v.w);
    ((uint2*)dst)[j] = r.u;
}

// ==================== router (one warp per token) ====================
__global__ void k_router(const float* __restrict__ x, const float* __restrict__ gw) {
    __shared__ float sgw[NE * NH];
    __shared__ float sprob[NE];
    __shared__ float sz;
    int tid = threadIdx.x;
    for (int i = tid; i < NE * NH; i += 256) sgw[i] = gw[i];
    if (tid < NE) sprob[tid] = 0.f;
    if (tid == 0) sz = 0.f;
    __syncthreads();

    int warp = tid >> 5, lane = tid & 31;
    int t = blockIdx.x * 8 + warp;

    float acc[NE];
#pragma unroll
    for (int e = 0; e < NE; e++) acc[e] = 0.f;
    const float* xr = x + (size_t)t * NH;
    for (int j = lane; j < NH; j += 32) {
        float xv = xr[j];
#pragma unroll
        for (int e = 0; e < NE; e++) acc[e] += xv * sgw[e * NH + j];
    }
#pragma unroll
    for (int e = 0; e < NE; e++)
#pragma unroll
        for (int off = 16; off > 0; off >>= 1)
            acc[e] += __shfl_xor_sync(0xffffffffu, acc[e], off);

    if (lane == 0) {
        float m = acc[0];
#pragma unroll
        for (int e = 1; e < NE; e++) m = fmaxf(m, acc[e]);
        float p[NE]; float s = 0.f;
#pragma unroll
        for (int e = 0; e < NE; e++) { p[e] = expf(acc[e] - m); s += p[e]; }
        float inv = 1.f / s;
#pragma unroll
        for (int e = 0; e < NE; e++) p[e] *= inv;

        int i0 = 0; float m0 = p[0];
#pragma unroll
        for (int e = 1; e < NE; e++) if (p[e] > m0) { m0 = p[e]; i0 = e; }
        int i1 = -1; float m1 = -1.f;
#pragma unroll
        for (int e = 0; e < NE; e++) if (e != i0 && p[e] > m1) { m1 = p[e]; i1 = e; }

        float wsum = m0 + m1;
        g_sel[2*t] = i0; g_sel[2*t+1] = i1;
        g_wt[2*t] = m0 / wsum; g_wt[2*t+1] = m1 / wsum;
        atomicAdd(&g_counts[i0], 1);
        atomicAdd(&g_counts[i1], 1);
#pragma unroll
        for (int e = 0; e < NE; e++) atomicAdd(&sprob[e], p[e]);
        float lse = m + logf(s);
        atomicAdd(&sz, lse * lse);
    }
    __syncthreads();
    if (tid < NE) atomicAdd(&g_probsum[tid], sprob[tid]);
    if (tid == 0) atomicAdd(&g_zsum, sz);
}

// ==================== fused offsets + scatter: one block per expert ========
__global__ void k_scatter8() {
    __shared__ int scur;
    __shared__ int soff;
    int e = blockIdx.x;
    int tid = threadIdx.x;
    if (tid == 0) {
        int s = 0;
        for (int q = 0; q < NE; q++) { if (q == e) break; s += g_counts[q]; }
        g_offsets[e] = s;
        soff = s;
        scur = 0;
    }
    __syncthreads();
    int off = soff;
    for (int idx = tid; idx < NPAIRS; idx += blockDim.x) {
        if (g_sel[idx] == e) {
            int pos = atomicAdd(&scur, 1);
            g_pair_tok[off + pos] = idx >> 1;
            g_pair_w[off + pos]   = g_wt[idx];
        }
    }
}

// ==================== HMMA GEMM kernels (R5 bodies: static smem, reg DB) ====
#define KB 32                 // K elements per stage
#define PITCH 80              // bytes per row: 64 data + 16 pad (conflict-free frags)
#define TILES_M 64

// ---- pass 1: gate/up GEMM + SwiGLU -> g_h (fp16) ----
// CTA tile M=128 x N=64 (two outputs); 256 threads; grid (TILES_M, NE*64)
__global__ void __launch_bounds__(256) k_ffn1() {
    // stage: A 128*80=10240, Bg 64*80=5120, Bu 5120 => 20480; x2 stages
    __shared__ __align__(16) char smc[2 * 20480];
    __shared__ int s_tok[128];

    int e  = blockIdx.y >> 6;
    int n0 = (blockIdx.y & 63) * 64;
    int row0 = blockIdx.x * 128;
    int cnt = g_counts[e];
    if (row0 >= cnt) return;
    int base = g_offsets[e];
    int tid = threadIdx.x;

    if (tid < 128) {
        int r = row0 + tid;
        s_tok[tid] = g_pair_tok[base + (r < cnt ? r : cnt - 1)];
    }
    __syncthreads();

    // loaders: A: 512 chunks (2/thread); Bg,Bu: 256 chunks (1/thread)
    int a_r0 = tid >> 2;            // row 0..63
    int a_r1 = (tid + 256) >> 2;    // row 64..127
    int a_c  = tid & 3;
    int b_r  = tid >> 2;            // 0..63
    const __half* pA0 = g_x_h + (size_t)s_tok[a_r0] * NH + a_c * 8;
    const __half* pA1 = g_x_h + (size_t)s_tok[a_r1] * NH + a_c * 8;
    const __half* pBg = g_wg_h + ((size_t)e * NI + n0 + b_r) * NH + a_c * 8;
    const __half* pBu = g_wu_h + ((size_t)e * NI + n0 + b_r) * NH + a_c * 8;
    uint32_t sA0 = a_r0 * PITCH + a_c * 16;
    uint32_t sA1 = a_r1 * PITCH + a_c * 16;
    uint32_t sBg = 10240 + b_r * PITCH + a_c * 16;
    uint32_t sBu = 15360 + b_r * PITCH + a_c * 16;

    int lane = tid & 31, w = tid >> 5;
    int wm = w >> 1, wn = w & 1;
    int r4 = lane >> 2, c2 = lane & 3;

    float ag[2][4][4], au[2][4][4];
#pragma unroll
    for (int i = 0; i < 2; i++)
#pragma unroll
        for (int j = 0; j < 4; j++)
#pragma unroll
            for (int q = 0; q < 4; q++) { ag[i][j][q] = 0.f; au[i][j][q] = 0.f; }

    uint4 vA0 = *(const uint4*)pA0;
    uint4 vA1 = *(const uint4*)pA1;
    uint4 vBg = *(const uint4*)pBg;
    uint4 vBu = *(const uint4*)pBu;

    const int KT = NH / KB;   // 32
    for (int kt = 0; kt < KT; kt++) {
        char* stg = smc + (kt & 1) * 20480;
        *(uint4*)(stg + sA0) = vA0;
        *(uint4*)(stg + sA1) = vA1;
        *(uint4*)(stg + sBg) = vBg;
        *(uint4*)(stg + sBu) = vBu;
        __syncthreads();

        if (kt + 1 < KT) {
            int ko = (kt + 1) * KB;
            vA0 = *(const uint4*)(pA0 + ko);
            vA1 = *(const uint4*)(pA1 + ko);
            vBg = *(const uint4*)(pBg + ko);
            vBu = *(const uint4*)(pBu + ko);
        }

        const char* A_s  = stg;
        const char* Bg_s = stg + 10240;
        const char* Bu_s = stg + 15360;
#pragma unroll
        for (int kk = 0; kk < 2; kk++) {
            uint32_t af[2][4];
#pragma unroll
            for (int i = 0; i < 2; i++) {
                const char* ab = A_s + (wm * 32 + i * 16 + r4) * PITCH + kk * 32 + c2 * 4;
                af[i][0] = *(const uint32_t*)(ab);
                af[i][1] = *(const uint32_t*)(ab + 8 * PITCH);
                af[i][2] = *(const uint32_t*)(ab + 16);
                af[i][3] = *(const uint32_t*)(ab + 8 * PITCH + 16);
            }
#pragma unroll
            for (int j = 0; j < 4; j++) {
                int n = wn * 32 + j * 8 + r4;
                const char* bb = Bg_s + n * PITCH + kk * 32 + c2 * 4;
                uint32_t bg[2], bu[2];
                bg[0] = *(const uint32_t*)(bb);
                bg[1] = *(const uint32_t*)(bb + 16);
                const char* ub = Bu_s + n * PITCH + kk * 32 + c2 * 4;
                bu[0] = *(const uint32_t*)(ub);
                bu[1] = *(const uint32_t*)(ub + 16);
#pragma unroll
                for (int i = 0; i < 2; i++) {
                    mma16816(ag[i][j], af[i], bg);
                    mma16816(au[i][j], af[i], bu);
                }
            }
        }
        __syncthreads();
    }

    // epilogue: h = silu(g)*u -> fp16
#pragma unroll
    for (int i = 0; i < 2; i++)
#pragma unroll
        for (int rr = 0; rr < 2; rr++) {
            int rl = wm * 32 + i * 16 + r4 + rr * 8;
            int r = row0 + rl;
            if (r < cnt) {
                __half* hrow = g_h + (size_t)(base + r) * NI;
#pragma unroll
                for (int j = 0; j < 4; j++) {
                    int col = n0 + wn * 32 + j * 8 + c2 * 2;
                    float g0 = ag[i][j][rr * 2], g1 = ag[i][j][rr * 2 + 1];
                    float u0 = au[i][j][rr * 2], u1 = au[i][j][rr * 2 + 1];
                    float h0 = g0 / (1.f + expf(-g0)) * u0;
                    float h1 = g1 / (1.f + expf(-g1)) * u1;
                    *(__half2*)(hrow + col) = __floats2half2_rn(h0, h1);
                }
            }
        }
}

// ---- zero the output (must run before k_ffn2's atomics) ----
__global__ void k_zero(float* __restrict__ out) {
    int idx = blockIdx.x * blockDim.x + threadIdx.x;
    const int n = NT * NH;
    for (int i = idx; i < n; i += gridDim.x * blockDim.x) out[i] = 0.f;
}

// ---- pass 2: out[tok] += w * (h @ Wd^T) ----
// CTA tile M=128 x N=128; 256 threads; grid (TILES_M, NE*8)
__global__ void __launch_bounds__(256) k_ffn2(float* __restrict__ out) {
    __shared__ __align__(16) char smc[2 * 20480];
    __shared__ int   s_tok[128];
    __shared__ float s_w[128];

    int e  = blockIdx.y >> 3;
    int n0 = (blockIdx.y & 7) * 128;
    int row0 = blockIdx.x * 128;
    int cnt = g_counts[e];
    if (row0 >= cnt) return;
    int base = g_offsets[e];
    int tid = threadIdx.x;

    if (tid < 128) {
        int r = row0 + tid;
        s_tok[tid] = (r < cnt) ? g_pair_tok[base + r] : 0;
        s_w[tid]   = (r < cnt) ? g_pair_w[base + r] : 0.f;
    }
    __syncthreads();

    int a_r0 = tid >> 2;
    int a_r1 = (tid + 256) >> 2;
    int a_c  = tid & 3;
    int rc0 = row0 + a_r0; if (rc0 >= cnt) rc0 = cnt - 1;
    int rc1 = row0 + a_r1; if (rc1 >= cnt) rc1 = cnt - 1;
    const __half* pA0 = g_h + (size_t)(base + rc0) * NI + a_c * 8;
    const __half* pA1 = g_h + (size_t)(base + rc1) * NI + a_c * 8;
    const __half* pB0 = g_wd_h + ((size_t)e * NH + n0 + a_r0) * NI + a_c * 8;
    const __half* pB1 = g_wd_h + ((size_t)e * NH + n0 + a_r1) * NI + a_c * 8;
    uint32_t sA0 = a_r0 * PITCH + a_c * 16;
    uint32_t sA1 = a_r1 * PITCH + a_c * 16;
    uint32_t sB0 = 10240 + sA0;
    uint32_t sB1 = 10240 + sA1;

    int lane = tid & 31, w = tid >> 5;
    int wm = w >> 1, wn = w & 1;
    int r4 = lane >> 2, c2 = lane & 3;

    float acc[2][8][4];
#pragma unroll
    for (int i = 0; i < 2; i++)
#pragma unroll
        for (int j = 0; j < 8; j++)
#pragma unroll
            for (int q = 0; q < 4; q++) acc[i][j][q] = 0.f;

    uint4 vA0 = *(const uint4*)pA0;
    uint4 vA1 = *(const uint4*)pA1;
    uint4 vB0 = *(const uint4*)pB0;
    uint4 vB1 = *(const uint4*)pB1;

    const int KT = NI / KB;   // 128
    for (int kt = 0; kt < KT; kt++) {
        char* stg = smc + (kt & 1) * 20480;
        *(uint4*)(stg + sA0) = vA0;
        *(uint4*)(stg + sA1) = vA1;
        *(uint4*)(stg + sB0) = vB0;
        *(uint4*)(stg + sB1) = vB1;
        __syncthreads();

        if (kt + 1 < KT) {
            int ko = (kt + 1) * KB;
            vA0 = *(const uint4*)(pA0 + ko);
            vA1 = *(const uint4*)(pA1 + ko);
            vB0 = *(const uint4*)(pB0 + ko);
            vB1 = *(const uint4*)(pB1 + ko);
        }

        const char* A_s = stg;
        const char* B_s = stg + 10240;
#pragma unroll
        for (int kk = 0; kk < 2; kk++) {
            uint32_t af[2][4];
#pragma unroll
            for (int i = 0; i < 2; i++) {
                const char* ab = A_s + (wm * 32 + i * 16 + r4) * PITCH + kk * 32 + c2 * 4;
                af[i][0] = *(const uint32_t*)(ab);
                af[i][1] = *(const uint32_t*)(ab + 8 * PITCH);
                af[i][2] = *(const uint32_t*)(ab + 16);
                af[i][3] = *(const uint32_t*)(ab + 8 * PITCH + 16);
            }
#pragma unroll
            for (int j = 0; j < 8; j++) {
                int n = wn * 64 + j * 8 + r4;
                const char* bb = B_s + n * PITCH + kk * 32 + c2 * 4;
                uint32_t b[2];
                b[0] = *(const uint32_t*)(bb);
                b[1] = *(const uint32_t*)(bb + 16);
#pragma unroll
                for (int i = 0; i < 2; i++) mma16816(acc[i][j], af[i], b);
            }
        }
        __syncthreads();
    }

    // epilogue: weighted atomic accumulate into out
#pragma unroll
    for (int i = 0; i < 2; i++)
#pragma unroll
        for (int rr = 0; rr < 2; rr++) {
            int rl = wm * 32 + i * 16 + r4 + rr * 8;
            if (row0 + rl < cnt) {
                int tok = s_tok[rl];
                float wt = s_w[rl];
                float* orow = out + (size_t)tok * NH + n0;
#pragma unroll
                for (int j = 0; j < 8; j++) {
                    int col = wn * 64 + j * 8 + c2 * 2;
                    atomicAdd(&orow[col],     wt * acc[i][j][rr * 2]);
                    atomicAdd(&orow[col + 1], wt * acc[i][j][rr * 2 + 1]);
                }
            }
        }
}

// ==================== losses ====================
__global__ void k_losses(float* __restrict__ out, int out_size) {
    if (threadIdx.x == 0 && blockIdx.x == 0) {
        float lb = 0.f;
        for (int e = 0; e < NE; e++)
            lb += ((float)g_counts[e] / (float)NT) * (g_probsum[e] / (float)NT);
        lb *= (float)NE * 0.01f;
        float z = g_zsum / (float)NT * 0.001f;
        if (out_size > NT * NH)     out[NT * NH]     = lb;
        if (out_size > NT * NH + 1) out[NT * NH + 1] = z;
    }
}

// ==================== launch ====================
extern "C" void kernel_launch(void* const* d_in, const int* in_sizes, int n_in,
                              void* d_out, int out_size) {
    const float* x  = (const float*)d_in[0];
    const float* gw = (const float*)d_in[1];
    const float* wg = (const float*)d_in[2];
    const float* wu = (const float*)d_in[3];
    const float* wd = (const float*)d_in[4];
    float* out = (float*)d_out;

    // launch 1: fused conversion + counter zeroing
    const long TOT4 = 3L * W4 + X4;
    k_conv<<<(int)((TOT4 + 255) / 256), 256>>>(wg, wu, wd, x);

    // launch 2: router
    k_router<<<NT / 8, 256>>>(x, gw);

    // launch 3: fused offsets + scatter
    k_scatter8<<<NE, 256>>>();

    // launch 4: pass-1 GEMM  (lands on the ncu capture slot)
    dim3 g1(TILES_M, NE * 64);
    k_ffn1<<<g1, 256>>>();

    // launch 5: zero output before pass-2 atomics
    k_zero<<<1024, 256>>>(out);

    // launch 6: pass-2 GEMM
    dim3 g2(TILES_M, NE * 8);
    k_ffn2<<<g2, 256>>>(out);

    // launch 7: losses
    k_losses<<<1, 32>>>(out, out_size);
}

// round 8
// speedup vs baseline: 1.2092x; 1.1946x over previous
#include <cuda_runtime.h>
#include <cuda_fp16.h>
#include <cstdint>
#include <math.h>

// Problem constants
#define NT 8192          // tokens = 4*2048
#define NH 1024          // hidden
#define NE 8             // experts
#define NI 4096          // intermediate
#define NPAIRS (2*NT)    // top-2 pairs

// ==================== PTX helpers ====================
__device__ __forceinline__ void mma16816(float* d, const uint32_t* a, const uint32_t* b) {
    asm volatile("mma.sync.aligned.m16n8k16.row.col.f32.f16.f16.f32 "
        "{%0,%1,%2,%3}, {%4,%5,%6,%7}, {%8,%9}, {%0,%1,%2,%3};"
        : "+f"(d[0]), "+f"(d[1]), "+f"(d[2]), "+f"(d[3])
        : "r"(a[0]), "r"(a[1]), "r"(a[2]), "r"(a[3]), "r"(b[0]), "r"(b[1]));
}
__device__ __forceinline__ uint32_t smem_u32(const void* p) {
    uint32_t a;
    asm("{ .reg .u64 t; cvta.to.shared.u64 t, %1; cvt.u32.u64 %0, t; }" : "=r"(a) : "l"(p));
    return a;
}
#define CP16(sm_addr, gptr) \
    asm volatile("cp.async.ca.shared.global [%0], [%1], 16;" \
                 :: "r"(sm_addr), "l"(gptr) : "memory")
#define CP_COMMIT() asm volatile("cp.async.commit_group;" ::: "memory")
#define CP_WAIT0()  asm volatile("cp.async.wait_group 0;" ::: "memory")

// ==================== device scratch (all 16B-aligned) ====================
__device__ __align__(16) int   g_sel[NT * 2];
__device__ __align__(16) float g_wt[NT * 2];
__device__ __align__(16) int   g_counts[NE];
__device__ __align__(16) int   g_offsets[NE];
__device__ __align__(16) float g_probsum[NE];
__device__ float g_zsum;
__device__ __align__(16) int   g_pair_tok[NPAIRS];
__device__ __align__(16) float g_pair_w[NPAIRS];

__device__ __align__(16) __half g_x_h[NT * NH];
__device__ __align__(16) __half g_wg_h[NE * NI * NH];
__device__ __align__(16) __half g_wu_h[NE * NI * NH];
__device__ __align__(16) __half g_wd_h[NE * NH * NI];
__device__ __align__(16) __half g_h[(size_t)NPAIRS * NI];

// ==================== fused fp32->fp16 conversion (single launch) ==========
#define W4 (NE * NI * NH / 4)
#define X4 (NT * NH / 4)
__global__ void k_conv(const float* __restrict__ wg, const float* __restrict__ wu,
                       const float* __restrict__ wd, const float* __restrict__ x) {
    long i = (long)blockIdx.x * blockDim.x + threadIdx.x;
    if (blockIdx.x == 0 && threadIdx.x < NE) {
        g_counts[threadIdx.x] = 0;
        g_probsum[threadIdx.x] = 0.f;
        if (threadIdx.x == 0) g_zsum = 0.f;
    }
    const float* src;
    __half* dst;
    long j;
    if (i < W4)            { src = wg; dst = g_wg_h; j = i; }
    else if (i < 2L * W4)  { src = wu; dst = g_wu_h; j = i - W4; }
    else if (i < 3L * W4)  { src = wd; dst = g_wd_h; j = i - 2L * W4; }
    else if (i < 3L * W4 + X4) { src = x; dst = g_x_h; j = i - 3L * W4; }
    else return;
    float4 v = ((const float4*)src)[j];
    union { __half h[4]; uint2 u; } r;
    r.h[0] = __float2half_rn(v.x);
    r.h[1] = __float2half_rn(v.y);
    r.h[2] = __float2half_rn(v.z);
    r.h[3] = __float2half_rn(v.w);
    ((uint2*)dst)[j] = r.u;
}

// ==================== router (one warp per token) ====================
__global__ void k_router(const float* __restrict__ x, const float* __restrict__ gw) {
    __shared__ float sgw[NE * NH];
    __shared__ float sprob[NE];
    __shared__ float sz;
    int tid = threadIdx.x;
    for (int i = tid; i < NE * NH; i += 256) sgw[i] = gw[i];
    if (tid < NE) sprob[tid] = 0.f;
    if (tid == 0) sz = 0.f;
    __syncthreads();

    int warp = tid >> 5, lane = tid & 31;
    int t = blockIdx.x * 8 + warp;

    float acc[NE];
#pragma unroll
    for (int e = 0; e < NE; e++) acc[e] = 0.f;
    const float* xr = x + (size_t)t * NH;
    for (int j = lane; j < NH; j += 32) {
        float xv = xr[j];
#pragma unroll
        for (int e = 0; e < NE; e++) acc[e] += xv * sgw[e * NH + j];
    }
#pragma unroll
    for (int e = 0; e < NE; e++)
#pragma unroll
        for (int off = 16; off > 0; off >>= 1)
            acc[e] += __shfl_xor_sync(0xffffffffu, acc[e], off);

    if (lane == 0) {
        float m = acc[0];
#pragma unroll
        for (int e = 1; e < NE; e++) m = fmaxf(m, acc[e]);
        float p[NE]; float s = 0.f;
#pragma unroll
        for (int e = 0; e < NE; e++) { p[e] = expf(acc[e] - m); s += p[e]; }
        float inv = 1.f / s;
#pragma unroll
        for (int e = 0; e < NE; e++) p[e] *= inv;

        int i0 = 0; float m0 = p[0];
#pragma unroll
        for (int e = 1; e < NE; e++) if (p[e] > m0) { m0 = p[e]; i0 = e; }
        int i1 = -1; float m1 = -1.f;
#pragma unroll
        for (int e = 0; e < NE; e++) if (e != i0 && p[e] > m1) { m1 = p[e]; i1 = e; }

        float wsum = m0 + m1;
        g_sel[2*t] = i0; g_sel[2*t+1] = i1;
        g_wt[2*t] = m0 / wsum; g_wt[2*t+1] = m1 / wsum;
        atomicAdd(&g_counts[i0], 1);
        atomicAdd(&g_counts[i1], 1);
#pragma unroll
        for (int e = 0; e < NE; e++) atomicAdd(&sprob[e], p[e]);
        float lse = m + logf(s);
        atomicAdd(&sz, lse * lse);
    }
    __syncthreads();
    if (tid < NE) atomicAdd(&g_probsum[tid], sprob[tid]);
    if (tid == 0) atomicAdd(&g_zsum, sz);
}

// ==================== fused offsets + scatter: one block per expert ========
__global__ void k_scatter8() {
    __shared__ int scur;
    __shared__ int soff;
    int e = blockIdx.x;
    int tid = threadIdx.x;
    if (tid == 0) {
        int s = 0;
        for (int q = 0; q < NE; q++) { if (q == e) break; s += g_counts[q]; }
        g_offsets[e] = s;
        soff = s;
        scur = 0;
    }
    __syncthreads();
    int off = soff;
    for (int idx = tid; idx < NPAIRS; idx += blockDim.x) {
        if (g_sel[idx] == e) {
            int pos = atomicAdd(&scur, 1);
            g_pair_tok[off + pos] = idx >> 1;
            g_pair_w[off + pos]   = g_wt[idx];
        }
    }
}

// ==================== HMMA GEMM kernels (64-tall warp tiles, cp.async) =====
#define KB 32                 // K elements per stage
#define PITCH 80              // bytes per smem row: 64 data + 16 pad
#define STAGE 20480
#define TILES_M 64

// ---- pass 1: gate/up GEMM + SwiGLU -> g_h (fp16) ----
// CTA tile M=128 x N=64 (x2 outputs); 128 threads = 4 warps of 64Mx32N(x2)
__global__ void __launch_bounds__(128) k_ffn1() {
    __shared__ __align__(16) char smc[2 * STAGE];   // A 10240 | Bg 5120 | Bu 5120
    __shared__ int s_tok[128];

    int e  = blockIdx.y >> 6;
    int n0 = (blockIdx.y & 63) * 64;
    int row0 = blockIdx.x * 128;
    int cnt = g_counts[e];
    if (row0 >= cnt) return;
    int base = g_offsets[e];
    int tid = threadIdx.x;

    {
        int r = row0 + tid;
        s_tok[tid] = g_pair_tok[base + (r < cnt ? r : cnt - 1)];
    }
    __syncthreads();

    uint32_t sb = smem_u32(smc);

    // cp.async loaders: A 4 chunks/thread, Bg 2, Bu 2 (16B chunks)
    const __half* pA[4]; uint32_t sA[4];
#pragma unroll
    for (int i = 0; i < 4; i++) {
        int idx = tid + 128 * i;
        int r = idx >> 2, c = idx & 3;
        pA[i] = g_x_h + (size_t)s_tok[r] * NH + c * 8;
        sA[i] = sb + r * PITCH + c * 16;
    }
    const __half* pB[4]; uint32_t sB[4];
#pragma unroll
    for (int i = 0; i < 2; i++) {
        int idx = tid + 128 * i;
        int r = idx >> 2, c = idx & 3;
        pB[i]     = g_wg_h + ((size_t)e * NI + n0 + r) * NH + c * 8;
        sB[i]     = sb + 10240 + r * PITCH + c * 16;
        pB[i + 2] = g_wu_h + ((size_t)e * NI + n0 + r) * NH + c * 8;
        sB[i + 2] = sb + 15360 + r * PITCH + c * 16;
    }

    int lane = tid & 31, w = tid >> 5;
    int wm = w & 1, wn = w >> 1;          // wm: 64-row half, wn: 32-col half
    int r4 = lane >> 2, c2 = lane & 3;

    float ag[4][4][4], au[4][4][4];
#pragma unroll
    for (int i = 0; i < 4; i++)
#pragma unroll
        for (int j = 0; j < 4; j++)
#pragma unroll
            for (int q = 0; q < 4; q++) { ag[i][j][q] = 0.f; au[i][j][q] = 0.f; }

    // prologue: stage 0
#pragma unroll
    for (int i = 0; i < 4; i++) CP16(sA[i], pA[i]);
#pragma unroll
    for (int i = 0; i < 4; i++) CP16(sB[i], pB[i]);
    CP_COMMIT();

    const int KT = NH / KB;   // 32
    for (int kt = 0; kt < KT; kt++) {
        CP_WAIT0();
        __syncthreads();
        if (kt + 1 < KT) {
            int ko = (kt + 1) * KB;
            uint32_t off = ((kt + 1) & 1) * STAGE;
#pragma unroll
            for (int i = 0; i < 4; i++) CP16(sA[i] + off, pA[i] + ko);
#pragma unroll
            for (int i = 0; i < 4; i++) CP16(sB[i] + off, pB[i] + ko);
            CP_COMMIT();
        }
        const char* stg = smc + (kt & 1) * STAGE;
#pragma unroll
        for (int kk = 0; kk < 2; kk++) {
            uint32_t af[4][4];
#pragma unroll
            for (int i = 0; i < 4; i++) {
                const char* ab = stg + (wm * 64 + i * 16 + r4) * PITCH + kk * 32 + c2 * 4;
                af[i][0] = *(const uint32_t*)(ab);
                af[i][1] = *(const uint32_t*)(ab + 8 * PITCH);
                af[i][2] = *(const uint32_t*)(ab + 16);
                af[i][3] = *(const uint32_t*)(ab + 8 * PITCH + 16);
            }
#pragma unroll
            for (int j = 0; j < 4; j++) {
                int n = wn * 32 + j * 8 + r4;
                const char* bb = stg + 10240 + n * PITCH + kk * 32 + c2 * 4;
                uint32_t bg[2], bu[2];
                bg[0] = *(const uint32_t*)(bb);
                bg[1] = *(const uint32_t*)(bb + 16);
                bu[0] = *(const uint32_t*)(bb + 5120);
                bu[1] = *(const uint32_t*)(bb + 5120 + 16);
#pragma unroll
                for (int i = 0; i < 4; i++) {
                    mma16816(ag[i][j], af[i], bg);
                    mma16816(au[i][j], af[i], bu);
                }
            }
        }
        // buffer being prefetched was last computed two phases back; the
        // barrier at the top of the next iteration publishes this compute.
    }

    // epilogue: h = silu(g)*u -> fp16
#pragma unroll
    for (int i = 0; i < 4; i++)
#pragma unroll
        for (int rr = 0; rr < 2; rr++) {
            int rl = wm * 64 + i * 16 + r4 + rr * 8;
            int r = row0 + rl;
            if (r < cnt) {
                __half* hrow = g_h + (size_t)(base + r) * NI;
#pragma unroll
                for (int j = 0; j < 4; j++) {
                    int col = n0 + wn * 32 + j * 8 + c2 * 2;
                    float g0 = ag[i][j][rr * 2], g1 = ag[i][j][rr * 2 + 1];
                    float u0 = au[i][j][rr * 2], u1 = au[i][j][rr * 2 + 1];
                    float h0 = g0 / (1.f + expf(-g0)) * u0;
                    float h1 = g1 / (1.f + expf(-g1)) * u1;
                    *(__half2*)(hrow + col) = __floats2half2_rn(h0, h1);
                }
            }
        }
}

// ---- zero the output (must run before k_ffn2's atomics) ----
__global__ void k_zero(float* __restrict__ out) {
    int idx = blockIdx.x * blockDim.x + threadIdx.x;
    const int n = NT * NH;
    for (int i = idx; i < n; i += gridDim.x * blockDim.x) out[i] = 0.f;
}

// ---- pass 2: out[tok] += w * (h @ Wd^T) ----
// CTA tile M=128 x N=128; 128 threads = 4 warps of 64Mx64N
__global__ void __launch_bounds__(128) k_ffn2(float* __restrict__ out) {
    __shared__ __align__(16) char smc[2 * STAGE];   // A 10240 | B 10240
    __shared__ int   s_tok[128];
    __shared__ float s_w[128];

    int e  = blockIdx.y >> 3;
    int n0 = (blockIdx.y & 7) * 128;
    int row0 = blockIdx.x * 128;
    int cnt = g_counts[e];
    if (row0 >= cnt) return;
    int base = g_offsets[e];
    int tid = threadIdx.x;

    {
        int r = row0 + tid;
        s_tok[tid] = (r < cnt) ? g_pair_tok[base + r] : 0;
        s_w[tid]   = (r < cnt) ? g_pair_w[base + r] : 0.f;
    }
    __syncthreads();

    uint32_t sb = smem_u32(smc);

    const __half* pA[4]; uint32_t sA[4];
    const __half* pB[4]; uint32_t sB[4];
#pragma unroll
    for (int i = 0; i < 4; i++) {
        int idx = tid + 128 * i;
        int r = idx >> 2, c = idx & 3;
        int rc = row0 + r; if (rc >= cnt) rc = cnt - 1;
        pA[i] = g_h + (size_t)(base + rc) * NI + c * 8;
        sA[i] = sb + r * PITCH + c * 16;
        pB[i] = g_wd_h + ((size_t)e * NH + n0 + r) * NI + c * 8;
        sB[i] = sb + 10240 + r * PITCH + c * 16;
    }

    int lane = tid & 31, w = tid >> 5;
    int wm = w & 1, wn = w >> 1;
    int r4 = lane >> 2, c2 = lane & 3;

    float acc[4][8][4];
#pragma unroll
    for (int i = 0; i < 4; i++)
#pragma unroll
        for (int j = 0; j < 8; j++)
#pragma unroll
            for (int q = 0; q < 4; q++) acc[i][j][q] = 0.f;

#pragma unroll
    for (int i = 0; i < 4; i++) { CP16(sA[i], pA[i]); CP16(sB[i], pB[i]); }
    CP_COMMIT();

    const int KT = NI / KB;   // 128
    for (int kt = 0; kt < KT; kt++) {
        CP_WAIT0();
        __syncthreads();
        if (kt + 1 < KT) {
            int ko = (kt + 1) * KB;
            uint32_t off = ((kt + 1) & 1) * STAGE;
#pragma unroll
            for (int i = 0; i < 4; i++) { CP16(sA[i] + off, pA[i] + ko); CP16(sB[i] + off, pB[i] + ko); }
            CP_COMMIT();
        }
        const char* stg = smc + (kt & 1) * STAGE;
#pragma unroll
        for (int kk = 0; kk < 2; kk++) {
            uint32_t af[4][4];
#pragma unroll
            for (int i = 0; i < 4; i++) {
                const char* ab = stg + (wm * 64 + i * 16 + r4) * PITCH + kk * 32 + c2 * 4;
                af[i][0] = *(const uint32_t*)(ab);
                af[i][1] = *(const uint32_t*)(ab + 8 * PITCH);
                af[i][2] = *(const uint32_t*)(ab + 16);
                af[i][3] = *(const uint32_t*)(ab + 8 * PITCH + 16);
            }
#pragma unroll
            for (int j = 0; j < 8; j++) {
                int n = wn * 64 + j * 8 + r4;
                const char* bb = stg + 10240 + n * PITCH + kk * 32 + c2 * 4;
                uint32_t b[2];
                b[0] = *(const uint32_t*)(bb);
                b[1] = *(const uint32_t*)(bb + 16);
#pragma unroll
                for (int i = 0; i < 4; i++) mma16816(acc[i][j], af[i], b);
            }
        }
    }

    // epilogue: weighted atomic accumulate into out
#pragma unroll
    for (int i = 0; i < 4; i++)
#pragma unroll
        for (int rr = 0; rr < 2; rr++) {
            int rl = wm * 64 + i * 16 + r4 + rr * 8;
            if (row0 + rl < cnt) {
                int tok = s_tok[rl];
                float wt = s_w[rl];
                float* orow = out + (size_t)tok * NH + n0;
#pragma unroll
                for (int j = 0; j < 8; j++) {
                    int col = wn * 64 + j * 8 + c2 * 2;
                    atomicAdd(&orow[col],     wt * acc[i][j][rr * 2]);
                    atomicAdd(&orow[col + 1], wt * acc[i][j][rr * 2 + 1]);
                }
            }
        }
}

// ==================== losses ====================
__global__ void k_losses(float* __restrict__ out, int out_size) {
    if (threadIdx.x == 0 && blockIdx.x == 0) {
        float lb = 0.f;
        for (int e = 0; e < NE; e++)
            lb += ((float)g_counts[e] / (float)NT) * (g_probsum[e] / (float)NT);
        lb *= (float)NE * 0.01f;
        float z = g_zsum / (float)NT * 0.001f;
        if (out_size > NT * NH)     out[NT * NH]     = lb;
        if (out_size > NT * NH + 1) out[NT * NH + 1] = z;
    }
}

// ==================== launch ====================
extern "C" void kernel_launch(void* const* d_in, const int* in_sizes, int n_in,
                              void* d_out, int out_size) {
    const float* x  = (const float*)d_in[0];
    const float* gw = (const float*)d_in[1];
    const float* wg = (const float*)d_in[2];
    const float* wu = (const float*)d_in[3];
    const float* wd = (const float*)d_in[4];
    float* out = (float*)d_out;

    const long TOT4 = 3L * W4 + X4;
    k_conv<<<(int)((TOT4 + 255) / 256), 256>>>(wg, wu, wd, x);
    k_router<<<NT / 8, 256>>>(x, gw);
    k_scatter8<<<NE, 256>>>();

    dim3 g1(TILES_M, NE * 64);        // launch 4: on the ncu capture slot
    k_ffn1<<<g1, 128>>>();

    k_zero<<<1024, 256>>>(out);

    dim3 g2(TILES_M, NE * 8);
    k_ffn2<<<g2, 128>>>(out);

    k_losses<<<1, 32>>>(out, out_size);
}

// round 9
// speedup vs baseline: 1.2372x; 1.0231x over previous
#include <cuda_runtime.h>
#include <cuda_fp16.h>
#include <cstdint>
#include <math.h>

// Problem constants
#define NT 8192          // tokens = 4*2048
#define NH 1024          // hidden
#define NE 8             // experts
#define NI 4096          // intermediate
#define NPAIRS (2*NT)    // top-2 pairs

// ==================== PTX helpers ====================
__device__ __forceinline__ void mma16816(float* d, const uint32_t* a, const uint32_t* b) {
    asm volatile("mma.sync.aligned.m16n8k16.row.col.f32.f16.f16.f32 "
        "{%0,%1,%2,%3}, {%4,%5,%6,%7}, {%8,%9}, {%0,%1,%2,%3};"
        : "+f"(d[0]), "+f"(d[1]), "+f"(d[2]), "+f"(d[3])
        : "r"(a[0]), "r"(a[1]), "r"(a[2]), "r"(a[3]), "r"(b[0]), "r"(b[1]));
}
__device__ __forceinline__ uint32_t smem_u32(const void* p) {
    uint32_t a;
    asm("{ .reg .u64 t; cvta.to.shared.u64 t, %1; cvt.u32.u64 %0, t; }" : "=r"(a) : "l"(p));
    return a;
}
#define CP16(sm_addr, gptr) \
    asm volatile("cp.async.ca.shared.global [%0], [%1], 16;" \
                 :: "r"(sm_addr), "l"(gptr) : "memory")
#define CP_COMMIT() asm volatile("cp.async.commit_group;" ::: "memory")
#define CP_WAIT0()  asm volatile("cp.async.wait_group 0;" ::: "memory")

// ==================== device scratch (all 16B-aligned) ====================
__device__ __align__(16) int   g_sel[NT * 2];
__device__ __align__(16) float g_wt[NT * 2];
__device__ __align__(16) int   g_counts[NE];
__device__ __align__(16) int   g_offsets[NE];
__device__ __align__(16) float g_probsum[NE];
__device__ float g_zsum;
__device__ __align__(16) int   g_pair_tok[NPAIRS];
__device__ __align__(16) float g_pair_w[NPAIRS];

__device__ __align__(16) __half g_x_h[NT * NH];
__device__ __align__(16) __half g_wg_h[NE * NI * NH];
__device__ __align__(16) __half g_wu_h[NE * NI * NH];
__device__ __align__(16) __half g_wd_h[NE * NH * NI];
__device__ __align__(16) __half g_h[(size_t)NPAIRS * NI];

// ==================== fused fp32->fp16 conversion + out zeroing ============
#define W4 (NE * NI * NH / 4)
#define X4 (NT * NH / 4)
#define O4 (NT * NH / 4)
__global__ void k_conv(const float* __restrict__ wg, const float* __restrict__ wu,
                       const float* __restrict__ wd, const float* __restrict__ x,
                       float* __restrict__ out) {
    long i = (long)blockIdx.x * blockDim.x + threadIdx.x;
    if (blockIdx.x == 0 && threadIdx.x < NE) {
        g_counts[threadIdx.x] = 0;
        g_probsum[threadIdx.x] = 0.f;
        if (threadIdx.x == 0) g_zsum = 0.f;
    }
    const float* src;
    __half* dst;
    long j;
    if (i < W4)            { src = wg; dst = g_wg_h; j = i; }
    else if (i < 2L * W4)  { src = wu; dst = g_wu_h; j = i - W4; }
    else if (i < 3L * W4)  { src = wd; dst = g_wd_h; j = i - 2L * W4; }
    else if (i < 3L * W4 + X4) { src = x; dst = g_x_h; j = i - 3L * W4; }
    else if (i < 3L * W4 + X4 + O4) {
        j = i - (3L * W4 + X4);
        ((float4*)out)[j] = make_float4(0.f, 0.f, 0.f, 0.f);
        return;
    }
    else return;
    float4 v = ((const float4*)src)[j];
    union { __half h[4]; uint2 u; } r;
    r.h[0] = __float2half_rn(v.x);
    r.h[1] = __float2half_rn(v.y);
    r.h[2] = __float2half_rn(v.z);
    r.h[3] = __float2half_rn(v.w);
    ((uint2*)dst)[j] = r.u;
}

// ==================== router (one warp per token) ====================
__global__ void k_router(const float* __restrict__ x, const float* __restrict__ gw) {
    __shared__ float sgw[NE * NH];
    __shared__ float sprob[NE];
    __shared__ float sz;
    int tid = threadIdx.x;
    for (int i = tid; i < NE * NH; i += 256) sgw[i] = gw[i];
    if (tid < NE) sprob[tid] = 0.f;
    if (tid == 0) sz = 0.f;
    __syncthreads();

    int warp = tid >> 5, lane = tid & 31;
    int t = blockIdx.x * 8 + warp;

    float acc[NE];
#pragma unroll
    for (int e = 0; e < NE; e++) acc[e] = 0.f;
    const float* xr = x + (size_t)t * NH;
    for (int j = lane; j < NH; j += 32) {
        float xv = xr[j];
#pragma unroll
        for (int e = 0; e < NE; e++) acc[e] += xv * sgw[e * NH + j];
    }
#pragma unroll
    for (int e = 0; e < NE; e++)
#pragma unroll
        for (int off = 16; off > 0; off >>= 1)
            acc[e] += __shfl_xor_sync(0xffffffffu, acc[e], off);

    if (lane == 0) {
        float m = acc[0];
#pragma unroll
        for (int e = 1; e < NE; e++) m = fmaxf(m, acc[e]);
        float p[NE]; float s = 0.f;
#pragma unroll
        for (int e = 0; e < NE; e++) { p[e] = expf(acc[e] - m); s += p[e]; }
        float inv = 1.f / s;
#pragma unroll
        for (int e = 0; e < NE; e++) p[e] *= inv;

        int i0 = 0; float m0 = p[0];
#pragma unroll
        for (int e = 1; e < NE; e++) if (p[e] > m0) { m0 = p[e]; i0 = e; }
        int i1 = -1; float m1 = -1.f;
#pragma unroll
        for (int e = 0; e < NE; e++) if (e != i0 && p[e] > m1) { m1 = p[e]; i1 = e; }

        float wsum = m0 + m1;
        g_sel[2*t] = i0; g_sel[2*t+1] = i1;
        g_wt[2*t] = m0 / wsum; g_wt[2*t+1] = m1 / wsum;
        atomicAdd(&g_counts[i0], 1);
        atomicAdd(&g_counts[i1], 1);
#pragma unroll
        for (int e = 0; e < NE; e++) atomicAdd(&sprob[e], p[e]);
        float lse = m + logf(s);
        atomicAdd(&sz, lse * lse);
    }
    __syncthreads();
    if (tid < NE) atomicAdd(&g_probsum[tid], sprob[tid]);
    if (tid == 0) atomicAdd(&g_zsum, sz);
}

// ==================== fused offsets + scatter: one block per expert ========
__global__ void k_scatter8() {
    __shared__ int scur;
    __shared__ int soff;
    int e = blockIdx.x;
    int tid = threadIdx.x;
    if (tid == 0) {
        int s = 0;
        for (int q = 0; q < NE; q++) { if (q == e) break; s += g_counts[q]; }
        g_offsets[e] = s;
        soff = s;
        scur = 0;
    }
    __syncthreads();
    int off = soff;
    for (int idx = tid; idx < NPAIRS; idx += blockDim.x) {
        if (g_sel[idx] == e) {
            int pos = atomicAdd(&scur, 1);
            g_pair_tok[off + pos] = idx >> 1;
            g_pair_w[off + pos]   = g_wt[idx];
        }
    }
}

// ==================== HMMA GEMM kernels (64-tall warp tiles, cp.async) =====
#define KB 32                 // K elements per stage
#define PITCH 80              // bytes per smem row: 64 data + 16 pad
#define STAGE 20480
#define TILES_M 64

// ---- pass 1: gate/up GEMM + SwiGLU -> g_h (fp16) ----
// CTA tile M=128 x N=64 (x2 outputs); 128 threads = 4 warps of 64Mx32N(x2)
__global__ void __launch_bounds__(128, 3) k_ffn1() {
    __shared__ __align__(16) char smc[2 * STAGE];   // A 10240 | Bg 5120 | Bu 5120
    __shared__ int s_tok[128];

    int e  = blockIdx.y >> 6;
    int n0 = (blockIdx.y & 63) * 64;
    int row0 = blockIdx.x * 128;
    int cnt = g_counts[e];
    if (row0 >= cnt) return;
    int base = g_offsets[e];
    int tid = threadIdx.x;

    {
        int r = row0 + tid;
        s_tok[tid] = g_pair_tok[base + (r < cnt ? r : cnt - 1)];
    }
    __syncthreads();

    uint32_t sb = smem_u32(smc);

    // cp.async loaders: A 4 chunks/thread, Bg 2, Bu 2 (16B chunks)
    const __half* pA[4]; uint32_t sA[4];
#pragma unroll
    for (int i = 0; i < 4; i++) {
        int idx = tid + 128 * i;
        int r = idx >> 2, c = idx & 3;
        pA[i] = g_x_h + (size_t)s_tok[r] * NH + c * 8;
        sA[i] = sb + r * PITCH + c * 16;
    }
    const __half* pB[4]; uint32_t sB[4];
#pragma unroll
    for (int i = 0; i < 2; i++) {
        int idx = tid + 128 * i;
        int r = idx >> 2, c = idx & 3;
        pB[i]     = g_wg_h + ((size_t)e * NI + n0 + r) * NH + c * 8;
        sB[i]     = sb + 10240 + r * PITCH + c * 16;
        pB[i + 2] = g_wu_h + ((size_t)e * NI + n0 + r) * NH + c * 8;
        sB[i + 2] = sb + 15360 + r * PITCH + c * 16;
    }

    int lane = tid & 31, w = tid >> 5;
    int wm = w & 1, wn = w >> 1;          // wm: 64-row half, wn: 32-col half
    int r4 = lane >> 2, c2 = lane & 3;

    float ag[4][4][4], au[4][4][4];
#pragma unroll
    for (int i = 0; i < 4; i++)
#pragma unroll
        for (int j = 0; j < 4; j++)
#pragma unroll
            for (int q = 0; q < 4; q++) { ag[i][j][q] = 0.f; au[i][j][q] = 0.f; }

    // prologue: stage 0
#pragma unroll
    for (int i = 0; i < 4; i++) CP16(sA[i], pA[i]);
#pragma unroll
    for (int i = 0; i < 4; i++) CP16(sB[i], pB[i]);
    CP_COMMIT();

    const int KT = NH / KB;   // 32
    for (int kt = 0; kt < KT; kt++) {
        CP_WAIT0();
        __syncthreads();
        if (kt + 1 < KT) {
            int ko = (kt + 1) * KB;
            uint32_t off = ((kt + 1) & 1) * STAGE;
#pragma unroll
            for (int i = 0; i < 4; i++) CP16(sA[i] + off, pA[i] + ko);
#pragma unroll
            for (int i = 0; i < 4; i++) CP16(sB[i] + off, pB[i] + ko);
            CP_COMMIT();
        }
        const char* stg = smc + (kt & 1) * STAGE;
#pragma unroll
        for (int kk = 0; kk < 2; kk++) {
            uint32_t af[4][4];
#pragma unroll
            for (int i = 0; i < 4; i++) {
                const char* ab = stg + (wm * 64 + i * 16 + r4) * PITCH + kk * 32 + c2 * 4;
                af[i][0] = *(const uint32_t*)(ab);
                af[i][1] = *(const uint32_t*)(ab + 8 * PITCH);
                af[i][2] = *(const uint32_t*)(ab + 16);
                af[i][3] = *(const uint32_t*)(ab + 8 * PITCH + 16);
            }
#pragma unroll
            for (int j = 0; j < 4; j++) {
                int n = wn * 32 + j * 8 + r4;
                const char* bb = stg + 10240 + n * PITCH + kk * 32 + c2 * 4;
                uint32_t bg[2], bu[2];
                bg[0] = *(const uint32_t*)(bb);
                bg[1] = *(const uint32_t*)(bb + 16);
                bu[0] = *(const uint32_t*)(bb + 5120);
                bu[1] = *(const uint32_t*)(bb + 5120 + 16);
#pragma unroll
                for (int i = 0; i < 4; i++) {
                    mma16816(ag[i][j], af[i], bg);
                    mma16816(au[i][j], af[i], bu);
                }
            }
        }
    }

    // epilogue: h = silu(g)*u -> fp16
#pragma unroll
    for (int i = 0; i < 4; i++)
#pragma unroll
        for (int rr = 0; rr < 2; rr++) {
            int rl = wm * 64 + i * 16 + r4 + rr * 8;
            int r = row0 + rl;
            if (r < cnt) {
                __half* hrow = g_h + (size_t)(base + r) * NI;
#pragma unroll
                for (int j = 0; j < 4; j++) {
                    int col = n0 + wn * 32 + j * 8 + c2 * 2;
                    float g0 = ag[i][j][rr * 2], g1 = ag[i][j][rr * 2 + 1];
                    float u0 = au[i][j][rr * 2], u1 = au[i][j][rr * 2 + 1];
                    float h0 = g0 / (1.f + expf(-g0)) * u0;
                    float h1 = g1 / (1.f + expf(-g1)) * u1;
                    *(__half2*)(hrow + col) = __floats2half2_rn(h0, h1);
                }
            }
        }
}

// ---- pass 2: out[tok] += w * (h @ Wd^T) ----
// CTA tile M=128 x N=128; 128 threads = 4 warps of 64Mx64N
__global__ void __launch_bounds__(128, 3) k_ffn2(float* __restrict__ out) {
    __shared__ __align__(16) char smc[2 * STAGE];   // A 10240 | B 10240
    __shared__ int   s_tok[128];
    __shared__ float s_w[128];

    int e  = blockIdx.y >> 3;
    int n0 = (blockIdx.y & 7) * 128;
    int row0 = blockIdx.x * 128;
    int cnt = g_counts[e];
    if (row0 >= cnt) return;
    int base = g_offsets[e];
    int tid = threadIdx.x;

    {
        int r = row0 + tid;
        s_tok[tid] = (r < cnt) ? g_pair_tok[base + r] : 0;
        s_w[tid]   = (r < cnt) ? g_pair_w[base + r] : 0.f;
    }
    __syncthreads();

    uint32_t sb = smem_u32(smc);

    const __half* pA[4]; uint32_t sA[4];
    const __half* pB[4]; uint32_t sB[4];
#pragma unroll
    for (int i = 0; i < 4; i++) {
        int idx = tid + 128 * i;
        int r = idx >> 2, c = idx & 3;
        int rc = row0 + r; if (rc >= cnt) rc = cnt - 1;
        pA[i] = g_h + (size_t)(base + rc) * NI + c * 8;
        sA[i] = sb + r * PITCH + c * 16;
        pB[i] = g_wd_h + ((size_t)e * NH + n0 + r) * NI + c * 8;
        sB[i] = sb + 10240 + r * PITCH + c * 16;
    }

    int lane = tid & 31, w = tid >> 5;
    int wm = w & 1, wn = w >> 1;
    int r4 = lane >> 2, c2 = lane & 3;

    float acc[4][8][4];
#pragma unroll
    for (int i = 0; i < 4; i++)
#pragma unroll
        for (int j = 0; j < 8; j++)
#pragma unroll
            for (int q = 0; q < 4; q++) acc[i][j][q] = 0.f;

#pragma unroll
    for (int i = 0; i < 4; i++) { CP16(sA[i], pA[i]); CP16(sB[i], pB[i]); }
    CP_COMMIT();

    const int KT = NI / KB;   // 128
    for (int kt = 0; kt < KT; kt++) {
        CP_WAIT0();
        __syncthreads();
        if (kt + 1 < KT) {
            int ko = (kt + 1) * KB;
            uint32_t off = ((kt + 1) & 1) * STAGE;
#pragma unroll
            for (int i = 0; i < 4; i++) { CP16(sA[i] + off, pA[i] + ko); CP16(sB[i] + off, pB[i] + ko); }
            CP_COMMIT();
        }
        const char* stg = smc + (kt & 1) * STAGE;
#pragma unroll
        for (int kk = 0; kk < 2; kk++) {
            uint32_t af[4][4];
#pragma unroll
            for (int i = 0; i < 4; i++) {
                const char* ab = stg + (wm * 64 + i * 16 + r4) * PITCH + kk * 32 + c2 * 4;
                af[i][0] = *(const uint32_t*)(ab);
                af[i][1] = *(const uint32_t*)(ab + 8 * PITCH);
                af[i][2] = *(const uint32_t*)(ab + 16);
                af[i][3] = *(const uint32_t*)(ab + 8 * PITCH + 16);
            }
#pragma unroll
            for (int j = 0; j < 8; j++) {
                int n = wn * 64 + j * 8 + r4;
                const char* bb = stg + 10240 + n * PITCH + kk * 32 + c2 * 4;
                uint32_t b[2];
                b[0] = *(const uint32_t*)(bb);
                b[1] = *(const uint32_t*)(bb + 16);
#pragma unroll
                for (int i = 0; i < 4; i++) mma16816(acc[i][j], af[i], b);
            }
        }
    }

    // epilogue: weighted atomic accumulate into out
#pragma unroll
    for (int i = 0; i < 4; i++)
#pragma unroll
        for (int rr = 0; rr < 2; rr++) {
            int rl = wm * 64 + i * 16 + r4 + rr * 8;
            if (row0 + rl < cnt) {
                int tok = s_tok[rl];
                float wt = s_w[rl];
                float* orow = out + (size_t)tok * NH + n0;
#pragma unroll
                for (int j = 0; j < 8; j++) {
                    int col = wn * 64 + j * 8 + c2 * 2;
                    atomicAdd(&orow[col],     wt * acc[i][j][rr * 2]);
                    atomicAdd(&orow[col + 1], wt * acc[i][j][rr * 2 + 1]);
                }
            }
        }
}

// ==================== losses ====================
__global__ void k_losses(float* __restrict__ out, int out_size) {
    if (threadIdx.x == 0 && blockIdx.x == 0) {
        float lb = 0.f;
        for (int e = 0; e < NE; e++)
            lb += ((float)g_counts[e] / (float)NT) * (g_probsum[e] / (float)NT);
        lb *= (float)NE * 0.01f;
        float z = g_zsum / (float)NT * 0.001f;
        if (out_size > NT * NH)     out[NT * NH]     = lb;
        if (out_size > NT * NH + 1) out[NT * NH + 1] = z;
    }
}

// ==================== launch ====================
extern "C" void kernel_launch(void* const* d_in, const int* in_sizes, int n_in,
                              void* d_out, int out_size) {
    const float* x  = (const float*)d_in[0];
    const float* gw = (const float*)d_in[1];
    const float* wg = (const float*)d_in[2];
    const float* wu = (const float*)d_in[3];
    const float* wd = (const float*)d_in[4];
    float* out = (float*)d_out;

    const long TOT4 = 3L * W4 + X4 + O4;
    k_conv<<<(int)((TOT4 + 255) / 256), 256>>>(wg, wu, wd, x, out);
    k_router<<<NT / 8, 256>>>(x, gw);
    k_scatter8<<<NE, 256>>>();

    dim3 g1(TILES_M, NE * 64);        // launch 4: on the ncu capture slot
    k_ffn1<<<g1, 128>>>();

    dim3 g2(TILES_M, NE * 8);
    k_ffn2<<<g2, 128>>>(out);

    k_losses<<<1, 32>>>(out, out_size);
}